// round 8
// baseline (speedup 1.0000x reference)
#include <cuda_runtime.h>

// Problem constants
#define T_STEPS 2048
#define B_TOT   256
#define H_DIM   512
#define D_IN    529            // 16 (x) + 512 (h) + 1 (cost)
#define WSTRIDE 548            // row stride floats: 137 16B-words (odd -> conflict-free lanes)
#define SLICE   68             // floats per j-slice (8 * 68 = 544 >= 529)
#define JS      8              // j-slices
#define NW      136            // 16B words covering 544 padded cols
#define CTAS_PER_CL 8
#define B_PER_CL    16
#define ROWS_PER_CTA 64
#define NTHREADS 512
#define XROW    20             // xc staging row: 16 x + 1 cost + pad

// ping-pong hidden-state buffers (L2 resident, 2MB total)
__device__ float g_hbuf[2][B_TOT * H_DIM];

__device__ __forceinline__ void ffma2(unsigned long long &d, unsigned long long a, unsigned long long b) {
    asm("fma.rn.f32x2 %0, %1, %2, %0;" : "+l"(d) : "l"(a), "l"(b));
}

__device__ __forceinline__ float unpack_sum(unsigned long long v) {
    float lo = __uint_as_float((unsigned)(v & 0xffffffffull));
    float hi = __uint_as_float((unsigned)(v >> 32));
    return lo + hi;
}

extern "C" __global__ void __launch_bounds__(NTHREADS, 1) __cluster_dims__(CTAS_PER_CL, 1, 1)
rnn_scan_kernel(const float* __restrict__ x,       // [B, T, 16]
                const float* __restrict__ hidden,  // [B, 512]
                const float* __restrict__ cost,    // [B, T]
                const float* __restrict__ Wo,      // [1, 529]
                const float* __restrict__ Wh,      // [512, 529]
                float* __restrict__ out)           // [B*T] outs, then [B*512] h_final
{
    extern __shared__ float smem[];
    float* W_s  = smem;                                   // 64 x 548
    float* in_s = W_s + ROWS_PER_CTA * WSTRIDE;           // 16 x 548 : [x(16)|h(512)|c(1)|0...]
    float* Wo_s = in_s + B_PER_CL * WSTRIDE;              // 548
    float* red  = Wo_s + WSTRIDE;                         // 8 jc x 16 b x 64 r = 8192
    float* xc_s = red + JS * B_PER_CL * ROWS_PER_CTA;     // 2 x 16 x 20

    const int tid   = threadIdx.x;
    const int lane  = tid & 31;
    const int w     = tid >> 5;                 // warp 0..15
    const int rg    = w & 1;                    // rowgroup
    const int jc    = w >> 1;                   // j-slice 0..7
    const int r_loc = rg * 32 + lane;           // local output row 0..63

    const int crank = blockIdx.x & (CTAS_PER_CL - 1);
    const int clid  = blockIdx.x >> 3;
    const int bbase = clid * B_PER_CL;
    const int row0  = crank * ROWS_PER_CTA;

    // ---- one-time: W chunk into SMEM (zero-padded), Wo, in_s pad, hidden -> g_hbuf[1], x0 ----
    for (int idx = tid; idx < ROWS_PER_CTA * WSTRIDE; idx += NTHREADS) {
        int r = idx / WSTRIDE;
        int c = idx - r * WSTRIDE;
        W_s[idx] = (c < D_IN) ? Wh[(size_t)(row0 + r) * D_IN + c] : 0.0f;
    }
    for (int idx = tid; idx < WSTRIDE; idx += NTHREADS)
        Wo_s[idx] = (idx < D_IN) ? Wo[idx] : 0.0f;
    for (int z = tid; z < B_PER_CL * (WSTRIDE - D_IN); z += NTHREADS) {
        int b = z / (WSTRIDE - D_IN);
        int c = D_IN + (z - b * (WSTRIDE - D_IN));
        in_s[b * WSTRIDE + c] = 0.0f;
    }
    for (int idx = tid; idx < 2 * H_DIM; idx += NTHREADS) {
        int bl  = idx >> 9;
        int col = idx & (H_DIM - 1);
        size_t off = (size_t)(bbase + crank * 2 + bl) * H_DIM + col;
        g_hbuf[1][off] = hidden[off];
    }
    if (tid < 128) {
        int b = tid >> 3, q = tid & 7;
        const float* xp = x + ((size_t)(bbase + b) * T_STEPS) * 16;
        xc_s[b * XROW + 2 * q]     = __ldg(xp + 2 * q);
        xc_s[b * XROW + 2 * q + 1] = __ldg(xp + 2 * q + 1);
        if (q == 0) xc_s[b * XROW + 16] = __ldg(cost + (size_t)(bbase + b) * T_STEPS);
    }
    __syncthreads();
    asm volatile("barrier.cluster.arrive.aligned;" ::: "memory");
    asm volatile("barrier.cluster.wait.aligned;"   ::: "memory");

    for (int t = 0; t < T_STEPS; ++t) {
        const int cur = t & 1;

        // ---- stage inter = [x_t | h | c_t] into in_s ----
        {
            // warp w stages h of batch row w
            const float4* hsrc = (const float4*)(g_hbuf[(t + 1) & 1] + (size_t)(bbase + w) * H_DIM);
            float4* hdst = (float4*)(in_s + w * WSTRIDE + 16);
            #pragma unroll
            for (int k = 0; k < 4; ++k)
                hdst[k * 32 + lane] = __ldcg(hsrc + k * 32 + lane);
        }
        if (tid < 256) {
            int b = tid >> 4, q = tid & 15;
            in_s[b * WSTRIDE + q] = xc_s[cur * B_PER_CL * XROW + b * XROW + q];
        } else if (tid < 256 + B_PER_CL) {
            int b = tid - 256;
            in_s[b * WSTRIDE + 528] = xc_s[cur * B_PER_CL * XROW + b * XROW + 16];
        }
        __syncthreads();

        // ---- prefetch x/cost for t+1 ----
        if (tid < 128 && t + 1 < T_STEPS) {
            int b = tid >> 3, q = tid & 7;
            float* dst = xc_s + ((t + 1) & 1) * B_PER_CL * XROW + b * XROW;
            const float* xp = x + ((size_t)(bbase + b) * T_STEPS + (t + 1)) * 16;
            dst[2 * q]     = __ldg(xp + 2 * q);
            dst[2 * q + 1] = __ldg(xp + 2 * q + 1);
            if (q == 0) dst[16] = __ldg(cost + (size_t)(bbase + b) * T_STEPS + (t + 1));
        }

        // ---- o_t = Wo . inter  (cluster CTA 0 only) ----
        if (crank == 0) {
            int b = w, js = lane;
            const ulonglong2* wop = (const ulonglong2*)Wo_s;
            const ulonglong2* hp  = (const ulonglong2*)(in_s + b * WSTRIDE);
            unsigned long long acc0 = 0ull;
            int w0 = js * 5;
            int w1 = min(NW, w0 + 5);
            for (int q = w0; q < w1; ++q) {
                ulonglong2 a = wop[q], h = hp[q];
                ffma2(acc0, a.x, h.x);
                ffma2(acc0, a.y, h.y);
            }
            float r = unpack_sum(acc0);
            r += __shfl_xor_sync(0xffffffffu, r, 1);
            r += __shfl_xor_sync(0xffffffffu, r, 2);
            r += __shfl_xor_sync(0xffffffffu, r, 4);
            r += __shfl_xor_sync(0xffffffffu, r, 8);
            r += __shfl_xor_sync(0xffffffffu, r, 16);
            if (js == 0) out[(size_t)(bbase + b) * T_STEPS + t] = r;
        }

        // ---- main matvec: lane = row; one W LDS.128 feeds all 16 batches ----
        unsigned long long acc[16];
        #pragma unroll
        for (int b = 0; b < 16; ++b) acc[b] = 0ull;

        const float* wb = W_s  + r_loc * WSTRIDE + jc * SLICE;
        const float* hb = in_s + jc * SLICE;

        #pragma unroll 1
        for (int kk = 0; kk < SLICE / 4; ++kk) {          // 17 x 16B chunks
            ulonglong2 Wv = *(const ulonglong2*)(wb + 4 * kk);
            #pragma unroll
            for (int b = 0; b < 16; ++b) {
                ulonglong2 hv = *(const ulonglong2*)(hb + b * WSTRIDE + 4 * kk);
                ffma2(acc[b], Wv.x, hv.x);
                ffma2(acc[b], Wv.y, hv.y);
            }
        }
        #pragma unroll
        for (int b = 0; b < 16; ++b)
            red[(jc * 16 + b) * 64 + r_loc] = unpack_sum(acc[b]);
        __syncthreads();

        // ---- reduce JS partials, write h_new ----
        {
            float* hdst = (t == T_STEPS - 1) ? (out + (size_t)B_TOT * T_STEPS)
                                             : g_hbuf[t & 1];
            #pragma unroll
            for (int pp = 0; pp < 2; ++pp) {
                int p = tid + pp * NTHREADS;              // 0..1023
                float s = 0.0f;
                #pragma unroll
                for (int j = 0; j < JS; ++j) s += red[j * 1024 + p];
                int b = p >> 6, r = p & 63;
                __stcg(hdst + (size_t)(bbase + b) * H_DIM + row0 + r, s);
            }
        }

        // ---- cluster barrier: publish h_new before next step reads ----
        asm volatile("barrier.cluster.arrive.aligned;" ::: "memory");
        asm volatile("barrier.cluster.wait.aligned;"   ::: "memory");
    }
}

extern "C" void kernel_launch(void* const* d_in, const int* in_sizes, int n_in,
                              void* d_out, int out_size) {
    const float* x      = (const float*)d_in[0];
    const float* hidden = (const float*)d_in[1];
    const float* cost   = (const float*)d_in[2];
    const float* Wo     = (const float*)d_in[3];
    const float* Wh     = (const float*)d_in[4];
    float* out = (float*)d_out;

    size_t smem = (size_t)(ROWS_PER_CTA * WSTRIDE + B_PER_CL * WSTRIDE + WSTRIDE
                           + JS * B_PER_CL * ROWS_PER_CTA + 2 * B_PER_CL * XROW) * sizeof(float);
    cudaFuncSetAttribute(rnn_scan_kernel, cudaFuncAttributeMaxDynamicSharedMemorySize, (int)smem);
    rnn_scan_kernel<<<128, NTHREADS, smem>>>(x, hidden, cost, Wo, Wh, out);
}

// round 9
// speedup vs baseline: 2.1517x; 2.1517x over previous
#include <cuda_runtime.h>
#include <cstdint>

// Problem constants
#define T_STEPS 2048
#define B_TOT   256
#define H_DIM   512
#define D_IN    529
#define KPAD    576            // padded K: 36 k16-steps
#define KSTEPS  36
#define ROWS_PER_CTA 64
#define B_PER_CL 16
#define NTHREADS 256
#define XROW 20
#define RQ 1088                // red floats per k-quarter: 16 batches * 68 stride

// SMEM word (uint32) offsets
#define W_WORDS (2*8*KSTEPS*32*2)     // 2 terms x 8 ntiles x 36 ks x 32 lanes x 2 regs = 36864 words
#define A_WORDS (3*KSTEPS*32*4)       // 3 terms x 36 x 32 x 4 regs = 13824 words
#define OFF_W 0
#define OFF_A (OFF_W + W_WORDS)
#define OFF_RED (OFF_A + A_WORDS)     // float[4*RQ]
#define OFF_WO (OFF_RED + 4*RQ)       // float[KPAD]
#define OFF_XC (OFF_WO + KPAD)        // float[2*16*XROW]
#define SMEM_WORDS (OFF_XC + 2*B_PER_CL*XROW)

#define W_WORD(term,nt,ks,ln,reg) (((((term)*8+(nt))*KSTEPS+(ks))*32+(ln))*2+(reg))
#define A_WORD(term,ks,ln)        (((term)*KSTEPS+(ks))*32+(ln))*4

// ping-pong hidden-state buffers (L2 resident, 2MB)
__device__ float g_hbuf[2][B_TOT * H_DIM];

__device__ __forceinline__ uint32_t f2bf(float f) {
    uint32_t u = __float_as_uint(f);
    return (u + 0x7FFFu + ((u >> 16) & 1u)) >> 16;     // round-to-nearest-even bf16
}
__device__ __forceinline__ float bf2f(uint32_t b) { return __uint_as_float(b << 16); }

__device__ __forceinline__ void mma16816(float c[4], uint4 a, uint2 b) {
    asm volatile(
        "mma.sync.aligned.m16n8k16.row.col.f32.bf16.bf16.f32 "
        "{%0,%1,%2,%3}, {%4,%5,%6,%7}, {%8,%9}, {%0,%1,%2,%3};"
        : "+f"(c[0]), "+f"(c[1]), "+f"(c[2]), "+f"(c[3])
        : "r"(a.x), "r"(a.y), "r"(a.z), "r"(a.w), "r"(b.x), "r"(b.y));
}

extern "C" __global__ void __launch_bounds__(NTHREADS, 1) __cluster_dims__(8, 1, 1)
rnn_mma_kernel(const float* __restrict__ x,       // [B, T, 16]
               const float* __restrict__ hidden,  // [B, 512]
               const float* __restrict__ cost,    // [B, T]
               const float* __restrict__ Wo,      // [1, 529]
               const float* __restrict__ Wh,      // [512, 529]
               float* __restrict__ out)           // [B*T] outs, then [B*512] h_final
{
    extern __shared__ uint32_t smw[];
    float* red  = (float*)(smw + OFF_RED);
    float* WoS  = (float*)(smw + OFF_WO);
    float* xcb  = (float*)(smw + OFF_XC);

    const int tid   = threadIdx.x;
    const int lane  = tid & 31;
    const int w     = tid >> 5;                 // warp 0..7
    const int crank = blockIdx.x & 7;
    const int clid  = blockIdx.x >> 3;
    const int bbase = clid * B_PER_CL;
    const int row0  = crank * ROWS_PER_CTA;

    // ---- one-time: W 2-term bf16 split into fragment-ordered SMEM ----
    for (int idx = tid; idx < ROWS_PER_CTA * KPAD; idx += NTHREADS) {
        int nl = idx / KPAD, c = idx - nl * KPAD;
        float v = (c < D_IN) ? Wh[(size_t)(row0 + nl) * D_IN + c] : 0.0f;
        uint32_t b0 = f2bf(v);
        uint32_t b1 = f2bf(v - bf2f(b0));
        int nt = nl >> 3, gp = nl & 7, ks = c >> 4, kk = c & 15;
        int reg = kk >> 3, tpp = (kk & 7) >> 1, half = kk & 1, lnp = gp * 4 + tpp;
        ((uint16_t*)smw)[(OFF_W + W_WORD(0, nt, ks, lnp, reg)) * 2 + half] = (uint16_t)b0;
        ((uint16_t*)smw)[(OFF_W + W_WORD(1, nt, ks, lnp, reg)) * 2 + half] = (uint16_t)b1;
    }
    for (int idx = tid; idx < A_WORDS; idx += NTHREADS) smw[OFF_A + idx] = 0u;
    for (int idx = tid; idx < KPAD; idx += NTHREADS) WoS[idx] = (idx < D_IN) ? Wo[idx] : 0.0f;
    for (int idx = tid; idx < 2 * H_DIM; idx += NTHREADS) {
        int bl = idx >> 9, col = idx & (H_DIM - 1);
        size_t off = (size_t)(bbase + crank * 2 + bl) * H_DIM + col;
        g_hbuf[1][off] = hidden[off];
    }
    if (tid < 128) {
        int b = tid >> 3, q = tid & 7;
        const float* xp = x + ((size_t)(bbase + b) * T_STEPS) * 16;
        xcb[b * XROW + 2 * q]     = __ldg(xp + 2 * q);
        xcb[b * XROW + 2 * q + 1] = __ldg(xp + 2 * q + 1);
        if (q == 0) xcb[b * XROW + 16] = __ldg(cost + (size_t)(bbase + b) * T_STEPS);
    }
    __syncthreads();
    asm volatile("barrier.cluster.arrive.aligned;" ::: "memory");
    asm volatile("barrier.cluster.wait.aligned;"   ::: "memory");

    const int qk  = w & 3;        // compute: k-quarter
    const int nh  = w >> 2;       // compute: n-half
    const int sbl = (tid & 31) >> 2;   // staging: batch low (0..7)
    const int stp = tid & 3;           // staging: t-in-group
    const int sks = tid >> 5;          // staging: ks group (0..7)

    for (int t = 0; t < T_STEPS; ++t) {
        const int ppr = (t + 1) & 1, ppw = t & 1, cur = t & 1;
        const float* xcc = xcb + cur * B_PER_CL * XROW;

        // ---- stage inter 3-term bf16 fragments (lane-consecutive STS.128) ----
        for (int ks = sks; ks < 34; ks += 8) {
            float v[4][2];
            #pragma unroll
            for (int rr = 0; rr < 4; ++rr) {
                int b = sbl + (rr & 1) * 8;
                int c = ks * 16 + ((rr >> 1) * 8) + 2 * stp;
                float v0, v1;
                if (c < 16)      { v0 = xcc[b * XROW + c]; v1 = xcc[b * XROW + c + 1]; }
                else if (c < 528) {
                    float2 h2 = __ldcg((const float2*)(g_hbuf[ppr] + (size_t)(bbase + b) * H_DIM + (c - 16)));
                    v0 = h2.x; v1 = h2.y;
                }
                else if (c == 528) { v0 = xcc[b * XROW + 16]; v1 = 0.0f; }
                else               { v0 = 0.0f; v1 = 0.0f; }
                v[rr][0] = v0; v[rr][1] = v1;
            }
            uint32_t p0[4], p1[4], p2[4];
            #pragma unroll
            for (int rr = 0; rr < 4; ++rr) {
                uint32_t a0 = f2bf(v[rr][0]); float r0 = v[rr][0] - bf2f(a0);
                uint32_t a1 = f2bf(r0);       float q0 = r0 - bf2f(a1);
                uint32_t a2 = f2bf(q0);
                uint32_t b0 = f2bf(v[rr][1]); float r1 = v[rr][1] - bf2f(b0);
                uint32_t b1 = f2bf(r1);       float q1 = r1 - bf2f(b1);
                uint32_t b2 = f2bf(q1);
                p0[rr] = a0 | (b0 << 16);
                p1[rr] = a1 | (b1 << 16);
                p2[rr] = a2 | (b2 << 16);
            }
            int ln = tid & 31;
            *(uint4*)&smw[OFF_A + A_WORD(0, ks, ln)] = make_uint4(p0[0], p0[1], p0[2], p0[3]);
            *(uint4*)&smw[OFF_A + A_WORD(1, ks, ln)] = make_uint4(p1[0], p1[1], p1[2], p1[3]);
            *(uint4*)&smw[OFF_A + A_WORD(2, ks, ln)] = make_uint4(p2[0], p2[1], p2[2], p2[3]);
        }
        __syncthreads();

        // ---- prefetch x/cost for t+1 ----
        if (tid < 128 && t + 1 < T_STEPS) {
            int b = tid >> 3, q = tid & 7;
            float* dst = xcb + ((t + 1) & 1) * B_PER_CL * XROW + b * XROW;
            const float* xp = x + ((size_t)(bbase + b) * T_STEPS + (t + 1)) * 16;
            dst[2 * q]     = __ldg(xp + 2 * q);
            dst[2 * q + 1] = __ldg(xp + 2 * q + 1);
            if (q == 0) dst[16] = __ldg(cost + (size_t)(bbase + b) * T_STEPS + (t + 1));
        }

        // ---- mma: warp = k-quarter x n-half; 9 ksteps x 4 n8-tiles x 5 passes ----
        float acc[4][4];
        #pragma unroll
        for (int i = 0; i < 4; ++i) { acc[i][0] = acc[i][1] = acc[i][2] = acc[i][3] = 0.0f; }
        #pragma unroll
        for (int s = 0; s < 9; ++s) {
            int ks = qk * 9 + s;
            uint4 I0 = *(const uint4*)&smw[OFF_A + A_WORD(0, ks, lane)];
            uint4 I1 = *(const uint4*)&smw[OFF_A + A_WORD(1, ks, lane)];
            uint4 I2 = *(const uint4*)&smw[OFF_A + A_WORD(2, ks, lane)];
            #pragma unroll
            for (int i = 0; i < 4; ++i) {
                int nt = nh * 4 + i;
                uint2 W0 = *(const uint2*)&smw[OFF_W + W_WORD(0, nt, ks, lane, 0)];
                uint2 W1 = *(const uint2*)&smw[OFF_W + W_WORD(1, nt, ks, lane, 0)];
                mma16816(acc[i], I0, W0);
                mma16816(acc[i], I1, W0);
                mma16816(acc[i], I0, W1);
                mma16816(acc[i], I1, W1);
                mma16816(acc[i], I2, W0);
            }
        }
        {
            int g = lane >> 2, tt = lane & 3;
            #pragma unroll
            for (int i = 0; i < 4; ++i) {
                int n0 = (nh * 4 + i) * 8 + 2 * tt;
                *(float2*)&red[qk * RQ + g * 68 + n0]       = make_float2(acc[i][0], acc[i][1]);
                *(float2*)&red[qk * RQ + (g + 8) * 68 + n0] = make_float2(acc[i][2], acc[i][3]);
            }
        }
        __syncthreads();

        // ---- reduce 4 k-quarter partials, publish h_new ----
        {
            int m = tid >> 4, n0 = (tid & 15) * 4;
            float4 s = make_float4(0.f, 0.f, 0.f, 0.f);
            #pragma unroll
            for (int qq = 0; qq < 4; ++qq) {
                float4 r4 = *(const float4*)&red[qq * RQ + m * 68 + n0];
                s.x += r4.x; s.y += r4.y; s.z += r4.z; s.w += r4.w;
            }
            float* hdst = (t == T_STEPS - 1) ? (out + (size_t)B_TOT * T_STEPS) : g_hbuf[ppw];
            __stcg((float4*)(hdst + (size_t)(bbase + m) * H_DIM + row0 + n0), s);
        }

        // ---- o_t fp32 (warp 0 of every CTA handles 2 batches; pre-update h) ----
        if (w == 0) {
            int bo = 2 * crank + (lane >> 4), li = lane & 15;
            const float* hrow = g_hbuf[ppr] + (size_t)(bbase + bo) * H_DIM;
            float r = 0.0f;
            #pragma unroll
            for (int j = 0; j < KSTEPS; ++j) {
                int c = li + 16 * j;
                float v;
                if (c < 16)       v = xcc[bo * XROW + c];
                else if (c < 528) v = __ldcg(hrow + (c - 16));
                else if (c == 528) v = xcc[bo * XROW + 16];
                else               v = 0.0f;
                r += WoS[c] * v;
            }
            r += __shfl_xor_sync(0xffffffffu, r, 1);
            r += __shfl_xor_sync(0xffffffffu, r, 2);
            r += __shfl_xor_sync(0xffffffffu, r, 4);
            r += __shfl_xor_sync(0xffffffffu, r, 8);
            if (li == 0) out[(size_t)(bbase + bo) * T_STEPS + t] = r;
        }

        // ---- cluster barrier: publish h_new before next step reads ----
        asm volatile("barrier.cluster.arrive.aligned;" ::: "memory");
        asm volatile("barrier.cluster.wait.aligned;"   ::: "memory");
    }
}

extern "C" void kernel_launch(void* const* d_in, const int* in_sizes, int n_in,
                              void* d_out, int out_size) {
    const float* x      = (const float*)d_in[0];
    const float* hidden = (const float*)d_in[1];
    const float* cost   = (const float*)d_in[2];
    const float* Wo     = (const float*)d_in[3];
    const float* Wh     = (const float*)d_in[4];
    float* out = (float*)d_out;

    size_t smem = (size_t)SMEM_WORDS * 4;   // 225,024 bytes
    cudaFuncSetAttribute(rnn_mma_kernel, cudaFuncAttributeMaxDynamicSharedMemorySize, (int)smem);
    rnn_mma_kernel<<<128, NTHREADS, smem>>>(x, hidden, cost, Wo, Wh, out);
}

// round 10
// speedup vs baseline: 2.2126x; 1.0283x over previous
#include <cuda_runtime.h>
#include <cstdint>

// Problem constants
#define T_STEPS 2048
#define B_TOT   256
#define H_DIM   512
#define D_IN    529
#define KPAD    576            // padded K cols (36 k16-steps allocated, 34 used)
#define KSTEPS  36
#define KS_USED 34
#define ROWS_PER_CTA 64
#define B_PER_CL 16
#define NTHREADS 512
#define XROW 20
#define RQ 1088                // red floats per k-half: 16 batches * 68 stride

// SMEM word (uint32) offsets
#define W_WORDS (2*8*KSTEPS*32*2)     // 2 terms x 8 ntiles x 36 ks x 32 lanes x 2 regs
#define A_WORDS (3*KSTEPS*32*4)       // 3 terms x 36 ks x 32 lanes x 4 regs
#define OFF_W 0
#define OFF_A (OFF_W + W_WORDS)
#define OFF_RED (OFF_A + A_WORDS)     // float[2*RQ]
#define OFF_WO (OFF_RED + 2*RQ)       // float[KPAD]
#define OFF_XC (OFF_WO + KPAD)        // float[2*16*XROW]
#define SMEM_WORDS (OFF_XC + 2*B_PER_CL*XROW)

#define W_WORD(term,nt,ks,ln,reg) (((((term)*8+(nt))*KSTEPS+(ks))*32+(ln))*2+(reg))
#define A_WORD(term,ks,ln)        (((term)*KSTEPS+(ks))*32+(ln))*4

// ping-pong hidden-state buffers (L2 resident, 2MB)
__device__ float g_hbuf[2][B_TOT * H_DIM];

__device__ __forceinline__ uint32_t f2bf(float f) {
    uint32_t u = __float_as_uint(f);
    return (u + 0x7FFFu + ((u >> 16) & 1u)) >> 16;
}
__device__ __forceinline__ float bf2f(uint32_t b) { return __uint_as_float(b << 16); }

// pack(lo=cvt(a), hi=cvt(b)) in one HW instruction
__device__ __forceinline__ uint32_t cvt2(float a, float b) {
    uint32_t r;
    asm("cvt.rn.satfinite.bf16x2.f32 %0, %1, %2;" : "=r"(r) : "f"(b), "f"(a));
    return r;
}

__device__ __forceinline__ void mma16816(float c[4], uint4 a, uint2 b) {
    asm volatile(
        "mma.sync.aligned.m16n8k16.row.col.f32.bf16.bf16.f32 "
        "{%0,%1,%2,%3}, {%4,%5,%6,%7}, {%8,%9}, {%0,%1,%2,%3};"
        : "+f"(c[0]), "+f"(c[1]), "+f"(c[2]), "+f"(c[3])
        : "r"(a.x), "r"(a.y), "r"(a.z), "r"(a.w), "r"(b.x), "r"(b.y));
}

extern "C" __global__ void __launch_bounds__(NTHREADS, 1) __cluster_dims__(8, 1, 1)
rnn_mma_kernel(const float* __restrict__ x,       // [B, T, 16]
               const float* __restrict__ hidden,  // [B, 512]
               const float* __restrict__ cost,    // [B, T]
               const float* __restrict__ Wo,      // [1, 529]
               const float* __restrict__ Wh,      // [512, 529]
               float* __restrict__ out)           // [B*T] outs, then [B*512] h_final
{
    extern __shared__ uint32_t smw[];
    float* red  = (float*)(smw + OFF_RED);
    float* WoS  = (float*)(smw + OFF_WO);
    float* xcb  = (float*)(smw + OFF_XC);

    const int tid   = threadIdx.x;
    const int lane  = tid & 31;
    const int w     = tid >> 5;                 // warp 0..15
    const int crank = blockIdx.x & 7;
    const int clid  = blockIdx.x >> 3;
    const int bbase = clid * B_PER_CL;
    const int row0  = crank * ROWS_PER_CTA;

    // ---- one-time: W 2-term bf16 split into fragment-ordered SMEM ----
    for (int idx = tid; idx < ROWS_PER_CTA * KPAD; idx += NTHREADS) {
        int nl = idx / KPAD, c = idx - nl * KPAD;
        float v = (c < D_IN) ? Wh[(size_t)(row0 + nl) * D_IN + c] : 0.0f;
        uint32_t b0 = f2bf(v);
        uint32_t b1 = f2bf(v - bf2f(b0));
        int nt = nl >> 3, gp = nl & 7, ks = c >> 4, kk = c & 15;
        int reg = kk >> 3, tpp = (kk & 7) >> 1, half = kk & 1, lnp = gp * 4 + tpp;
        ((uint16_t*)smw)[(OFF_W + W_WORD(0, nt, ks, lnp, reg)) * 2 + half] = (uint16_t)b0;
        ((uint16_t*)smw)[(OFF_W + W_WORD(1, nt, ks, lnp, reg)) * 2 + half] = (uint16_t)b1;
    }
    for (int idx = tid; idx < A_WORDS; idx += NTHREADS) smw[OFF_A + idx] = 0u;
    for (int idx = tid; idx < KPAD; idx += NTHREADS) WoS[idx] = (idx < D_IN) ? Wo[idx] : 0.0f;
    for (int idx = tid; idx < 2 * H_DIM; idx += NTHREADS) {
        int bl = idx >> 9, col = idx & (H_DIM - 1);
        size_t off = (size_t)(bbase + crank * 2 + bl) * H_DIM + col;
        g_hbuf[1][off] = hidden[off];
    }
    if (tid < 128) {
        int b = tid >> 3, q = tid & 7;
        const float* xp = x + ((size_t)(bbase + b) * T_STEPS) * 16;
        xcb[b * XROW + 2 * q]     = __ldg(xp + 2 * q);
        xcb[b * XROW + 2 * q + 1] = __ldg(xp + 2 * q + 1);
        if (q == 0) xcb[b * XROW + 16] = __ldg(cost + (size_t)(bbase + b) * T_STEPS);
    }
    __syncthreads();
    asm volatile("barrier.cluster.arrive.aligned;" ::: "memory");
    asm volatile("barrier.cluster.wait.aligned;"   ::: "memory");

    const int nt  = w & 7;        // compute: n-tile (8 rows)
    const int kh2 = w >> 3;       // compute: k-half
    const int sbl = lane >> 2;    // staging: batch low (0..7)
    const int stp = lane & 3;     // staging: t-in-group
    const int sks = tid >> 5;     // staging: ks group (0..15)

    for (int t = 0; t < T_STEPS; ++t) {
        const int ppr = (t + 1) & 1, ppw = t & 1, cur = t & 1;
        const float* xcc = xcb + cur * B_PER_CL * XROW;

        // ---- stage inter 3-term bf16 fragments (lane-consecutive STS.128) ----
        for (int ks = sks; ks < KS_USED; ks += 16) {
            float v[4][2];
            #pragma unroll
            for (int rr = 0; rr < 4; ++rr) {
                int b = sbl + (rr & 1) * 8;
                int c = ks * 16 + ((rr >> 1) * 8) + 2 * stp;
                float v0, v1;
                if (c < 16)      { v0 = xcc[b * XROW + c]; v1 = xcc[b * XROW + c + 1]; }
                else if (c < 528) {
                    float2 h2 = __ldcg((const float2*)(g_hbuf[ppr] + (size_t)(bbase + b) * H_DIM + (c - 16)));
                    v0 = h2.x; v1 = h2.y;
                }
                else if (c == 528) { v0 = xcc[b * XROW + 16]; v1 = 0.0f; }
                else               { v0 = 0.0f; v1 = 0.0f; }
                v[rr][0] = v0; v[rr][1] = v1;
            }
            uint32_t p0[4], p1[4], p2[4];
            #pragma unroll
            for (int rr = 0; rr < 4; ++rr) {
                uint32_t q0 = cvt2(v[rr][0], v[rr][1]);
                float r0 = v[rr][0] - __uint_as_float(q0 << 16);
                float r1 = v[rr][1] - __uint_as_float(q0 & 0xFFFF0000u);
                uint32_t q1 = cvt2(r0, r1);
                float s0 = r0 - __uint_as_float(q1 << 16);
                float s1 = r1 - __uint_as_float(q1 & 0xFFFF0000u);
                uint32_t q2 = cvt2(s0, s1);
                p0[rr] = q0; p1[rr] = q1; p2[rr] = q2;
            }
            *(uint4*)&smw[OFF_A + A_WORD(0, ks, lane)] = make_uint4(p0[0], p0[1], p0[2], p0[3]);
            *(uint4*)&smw[OFF_A + A_WORD(1, ks, lane)] = make_uint4(p1[0], p1[1], p1[2], p1[3]);
            *(uint4*)&smw[OFF_A + A_WORD(2, ks, lane)] = make_uint4(p2[0], p2[1], p2[2], p2[3]);
        }
        __syncthreads();

        // ---- prefetch x/cost for t+1 ----
        if (tid < 128 && t + 1 < T_STEPS) {
            int b = tid >> 3, q = tid & 7;
            float* dst = xcb + ((t + 1) & 1) * B_PER_CL * XROW + b * XROW;
            const float* xp = x + ((size_t)(bbase + b) * T_STEPS + (t + 1)) * 16;
            dst[2 * q]     = __ldg(xp + 2 * q);
            dst[2 * q + 1] = __ldg(xp + 2 * q + 1);
            if (q == 0) dst[16] = __ldg(cost + (size_t)(bbase + b) * T_STEPS + (t + 1));
        }

        // ---- mma: warp = n-tile x k-half; 17 ksteps x 5 passes ----
        float acc[4];
        acc[0] = acc[1] = acc[2] = acc[3] = 0.0f;
        #pragma unroll
        for (int s = 0; s < 17; ++s) {
            int ks = kh2 * 17 + s;
            uint4 I0 = *(const uint4*)&smw[OFF_A + A_WORD(0, ks, lane)];
            uint4 I1 = *(const uint4*)&smw[OFF_A + A_WORD(1, ks, lane)];
            uint4 I2 = *(const uint4*)&smw[OFF_A + A_WORD(2, ks, lane)];
            uint2 W0 = *(const uint2*)&smw[OFF_W + W_WORD(0, nt, ks, lane, 0)];
            uint2 W1 = *(const uint2*)&smw[OFF_W + W_WORD(1, nt, ks, lane, 0)];
            mma16816(acc, I0, W0);
            mma16816(acc, I1, W0);
            mma16816(acc, I0, W1);
            mma16816(acc, I1, W1);
            mma16816(acc, I2, W0);
        }
        {
            int g = lane >> 2, tt = lane & 3;
            int n0 = nt * 8 + 2 * tt;
            *(float2*)&red[kh2 * RQ + g * 68 + n0]       = make_float2(acc[0], acc[1]);
            *(float2*)&red[kh2 * RQ + (g + 8) * 68 + n0] = make_float2(acc[2], acc[3]);
        }
        __syncthreads();

        // ---- reduce 2 k-half partials, publish h_new ----
        {
            int m = tid >> 5, n0 = (tid & 31) * 2;
            float2 r0 = *(const float2*)&red[m * 68 + n0];
            float2 r1 = *(const float2*)&red[RQ + m * 68 + n0];
            float2 s = make_float2(r0.x + r1.x, r0.y + r1.y);
            float* hdst = (t == T_STEPS - 1) ? (out + (size_t)B_TOT * T_STEPS) : g_hbuf[ppw];
            __stcg((float2*)(hdst + (size_t)(bbase + m) * H_DIM + row0 + n0), s);
        }

        // ---- o_t fp32 (warp 0 of every CTA handles 2 batches; pre-update h) ----
        if (w == 0) {
            int bo = 2 * crank + (lane >> 4), li = lane & 15;
            const float* hrow = g_hbuf[ppr] + (size_t)(bbase + bo) * H_DIM;
            float r = 0.0f;
            #pragma unroll
            for (int j = 0; j < KS_USED; ++j) {
                int c = li + 16 * j;
                float v;
                if (c < 16)        v = xcc[bo * XROW + c];
                else if (c < 528)  v = __ldcg(hrow + (c - 16));
                else if (c == 528) v = xcc[bo * XROW + 16];
                else               v = 0.0f;
                r += WoS[c] * v;
            }
            r += __shfl_xor_sync(0xffffffffu, r, 1);
            r += __shfl_xor_sync(0xffffffffu, r, 2);
            r += __shfl_xor_sync(0xffffffffu, r, 4);
            r += __shfl_xor_sync(0xffffffffu, r, 8);
            if (li == 0) out[(size_t)(bbase + bo) * T_STEPS + t] = r;
        }

        // ---- cluster barrier: publish h_new before next step reads ----
        asm volatile("barrier.cluster.arrive.aligned;" ::: "memory");
        asm volatile("barrier.cluster.wait.aligned;"   ::: "memory");
    }
}

extern "C" void kernel_launch(void* const* d_in, const int* in_sizes, int n_in,
                              void* d_out, int out_size) {
    const float* x      = (const float*)d_in[0];
    const float* hidden = (const float*)d_in[1];
    const float* cost   = (const float*)d_in[2];
    const float* Wo     = (const float*)d_in[3];
    const float* Wh     = (const float*)d_in[4];
    float* out = (float*)d_out;

    size_t smem = (size_t)SMEM_WORDS * 4;
    cudaFuncSetAttribute(rnn_mma_kernel, cudaFuncAttributeMaxDynamicSharedMemorySize, (int)smem);
    rnn_mma_kernel<<<128, NTHREADS, smem>>>(x, hidden, cost, Wo, Wh, out);
}

// round 11
// speedup vs baseline: 2.9070x; 1.3138x over previous
#include <cuda_runtime.h>
#include <cstdint>

// Problem constants
#define T_STEPS 2048
#define B_TOT   256
#define H_DIM   512
#define D_IN    529
#define KPAD    544            // padded K cols = 34 k16-steps
#define KSTEPS  34
#define ROWS_PER_CTA 64
#define B_PER_CL 16
#define NCL 16
#define NTHREADS 512
#define XROW 20
#define RQ 1088                // red floats per k-half: 16 batches * 68 stride

// SMEM word (uint32) offsets
#define W_WORDS (2*8*KSTEPS*32*2)     // 2 terms x 8 ntiles x 34 ks x 32 lanes x 2 regs = 34816
#define A_WORDS (2*KSTEPS*32*4)       // 2 terms x 34 ks x 32 lanes x 4 regs = 8704
#define OFF_W 0
#define OFF_A (OFF_W + W_WORDS)
#define OFF_RED (OFF_A + A_WORDS)     // float[2*RQ]
#define OFF_WO (OFF_RED + 2*RQ)       // float[KPAD]
#define OFF_XC (OFF_WO + KPAD)        // float[2*16*XROW]
#define SMEM_WORDS (OFF_XC + 2*B_PER_CL*XROW)

#define W_WORD(term,nt,ks,ln,reg) (((((term)*8+(nt))*KSTEPS+(ks))*32+(ln))*2+(reg))
#define A2W(t2,ks,ln) ((((t2)*KSTEPS+(ks))*32+(ln))*4)

// f32 hidden ping-pong (for o_t and h_final)
__device__ float g_hbuf[2][B_TOT * H_DIM];
// fragment-ready bf16 2-term hidden ping-pong: [pp][cluster][term][32 ks x 32 lanes x 4 regs]
__device__ uint32_t g_hfrag[2][NCL][2][4096];

__device__ __forceinline__ uint32_t f2bf(float f) {
    uint32_t u = __float_as_uint(f);
    return (u + 0x7FFFu + ((u >> 16) & 1u)) >> 16;
}
__device__ __forceinline__ float bf2f(uint32_t b) { return __uint_as_float(b << 16); }

// pack {lo=bf16(a), hi=bf16(b)} in one HW cvt
__device__ __forceinline__ uint32_t cvt2(float a, float b) {
    uint32_t r;
    asm("cvt.rn.satfinite.bf16x2.f32 %0, %1, %2;" : "=r"(r) : "f"(b), "f"(a));
    return r;
}

__device__ __forceinline__ void mma16816(float c[4], uint4 a, uint2 b) {
    asm volatile(
        "mma.sync.aligned.m16n8k16.row.col.f32.bf16.bf16.f32 "
        "{%0,%1,%2,%3}, {%4,%5,%6,%7}, {%8,%9}, {%0,%1,%2,%3};"
        : "+f"(c[0]), "+f"(c[1]), "+f"(c[2]), "+f"(c[3])
        : "r"(a.x), "r"(a.y), "r"(a.z), "r"(a.w), "r"(b.x), "r"(b.y));
}

// split float2 into two packed bf16x2 terms
__device__ __forceinline__ void split2(float v0, float v1, uint32_t& q0, uint32_t& q1) {
    q0 = cvt2(v0, v1);
    float e0 = v0 - __uint_as_float(q0 << 16);
    float e1 = v1 - __uint_as_float(q0 & 0xFFFF0000u);
    q1 = cvt2(e0, e1);
}

extern "C" __global__ void __launch_bounds__(NTHREADS, 1) __cluster_dims__(8, 1, 1)
rnn_mma_kernel(const float* __restrict__ x,       // [B, T, 16]
               const float* __restrict__ hidden,  // [B, 512]
               const float* __restrict__ cost,    // [B, T]
               const float* __restrict__ Wo,      // [1, 529]
               const float* __restrict__ Wh,      // [512, 529]
               float* __restrict__ out)           // [B*T] outs, then [B*512] h_final
{
    extern __shared__ uint32_t smw[];
    float* red  = (float*)(smw + OFF_RED);
    float* WoS  = (float*)(smw + OFF_WO);
    float* xcb  = (float*)(smw + OFF_XC);

    const int tid   = threadIdx.x;
    const int lane  = tid & 31;
    const int w     = tid >> 5;                 // warp 0..15
    const int crank = blockIdx.x & 7;
    const int clid  = blockIdx.x >> 3;
    const int bbase = clid * B_PER_CL;
    const int row0  = crank * ROWS_PER_CTA;

    // ---- one-time: W 2-term bf16 split into fragment-ordered SMEM ----
    for (int idx = tid; idx < ROWS_PER_CTA * KPAD; idx += NTHREADS) {
        int nl = idx / KPAD, c = idx - nl * KPAD;
        float v = (c < D_IN) ? Wh[(size_t)(row0 + nl) * D_IN + c] : 0.0f;
        uint32_t b0 = f2bf(v);
        uint32_t b1 = f2bf(v - bf2f(b0));
        int nt = nl >> 3, gp = nl & 7, ks = c >> 4, kk = c & 15;
        int reg = kk >> 3, tpp = (kk & 7) >> 1, half = kk & 1, lnp = gp * 4 + tpp;
        ((uint16_t*)smw)[(OFF_W + W_WORD(0, nt, ks, lnp, reg)) * 2 + half] = (uint16_t)b0;
        ((uint16_t*)smw)[(OFF_W + W_WORD(1, nt, ks, lnp, reg)) * 2 + half] = (uint16_t)b1;
    }
    for (int idx = tid; idx < A_WORDS; idx += NTHREADS) smw[OFF_A + idx] = 0u;
    for (int idx = tid; idx < KPAD; idx += NTHREADS) WoS[idx] = (idx < D_IN) ? Wo[idx] : 0.0f;
    // f32 h0 for o_t
    for (int idx = tid; idx < 2 * H_DIM; idx += NTHREADS) {
        int bl = idx >> 9, col = idx & (H_DIM - 1);
        size_t off = (size_t)(bbase + crank * 2 + bl) * H_DIM + col;
        g_hbuf[1][off] = hidden[off];
    }
    // frag-form h0: this CTA's 64-row slice (global cols 16+row0 .. +63), all 16 batches
    {
        int m = tid >> 5, n0 = (tid & 31) * 2;
        float v0 = hidden[(size_t)(bbase + m) * H_DIM + row0 + n0];
        float v1 = hidden[(size_t)(bbase + m) * H_DIM + row0 + n0 + 1];
        uint32_t q0, q1;
        split2(v0, v1, q0, q1);
        int lane2 = (m & 7) * 4 + ((n0 >> 1) & 3);
        int rr = (m >> 3) | (((n0 >> 3) & 1) << 1);
        int widx = (row0 >> 4) * 128 + (((n0 >> 4) * 32 + lane2) * 4 + rr);
        g_hfrag[1][clid][0][widx] = q0;
        g_hfrag[1][clid][1][widx] = q1;
    }
    // x/cost t=0
    if (tid < 128) {
        int b = tid >> 3, q = tid & 7;
        const float* xp = x + ((size_t)(bbase + b) * T_STEPS) * 16;
        xcb[b * XROW + 2 * q]     = __ldg(xp + 2 * q);
        xcb[b * XROW + 2 * q + 1] = __ldg(xp + 2 * q + 1);
        if (q == 0) xcb[b * XROW + 16] = __ldg(cost + (size_t)(bbase + b) * T_STEPS);
    }
    __syncthreads();
    asm volatile("barrier.cluster.arrive.aligned;" ::: "memory");
    asm volatile("barrier.cluster.wait.aligned;"   ::: "memory");

    const int nt  = w & 7;        // compute: n-tile (8 rows)
    const int kh2 = w >> 3;       // compute: k-half

    for (int t = 0; t < T_STEPS; ++t) {
        const int ppr = (t + 1) & 1, ppw = t & 1, cur = t & 1;
        const float* xcc = xcb + cur * B_PER_CL * XROW;

        // ---- phase A: staging copy (warps 0-14) || o_t (warp 15) ----
        if (w == 15) {
            // o_t for this CTA's 2 batches, pre-update h (f32)
            int bo = 2 * crank + (lane >> 4), li = lane & 15;
            const float* hrow = g_hbuf[ppr] + (size_t)(bbase + bo) * H_DIM;
            float r = 0.0f;
            #pragma unroll
            for (int j = 0; j < KSTEPS; ++j) {
                int c = li + 16 * j;
                float v;
                if (c < 16)        v = xcc[bo * XROW + c];
                else if (c < 528)  v = __ldcg(hrow + (c - 16));
                else if (c == 528) v = xcc[bo * XROW + 16];
                else               v = 0.0f;
                r += WoS[c] * v;
            }
            r += __shfl_xor_sync(0xffffffffu, r, 1);
            r += __shfl_xor_sync(0xffffffffu, r, 2);
            r += __shfl_xor_sync(0xffffffffu, r, 4);
            r += __shfl_xor_sync(0xffffffffu, r, 8);
            if (li == 0) out[(size_t)(bbase + bo) * T_STEPS + t] = r;
        } else {
            // copy h frags (2 terms x 1024 uint4) from L2 into A buffer (ks 1..32)
            const uint4* gsrc = (const uint4*)g_hfrag[ppr][clid];
            for (int q = tid; q < 2048; q += 480) {
                int t2 = q >> 10, qq = q & 1023;
                uint4 v = __ldcg(gsrc + q);
                *(uint4*)&smw[OFF_A + (t2 * KSTEPS + 1) * 128 + qq * 4] = v;
            }
        }
        // x frags (ks0) and cost frags (ks33)
        if (tid < 128) {
            int m = tid >> 3, p = tid & 7;
            uint32_t q0, q1;
            split2(xcc[m * XROW + 2 * p], xcc[m * XROW + 2 * p + 1], q0, q1);
            int lane2 = (m & 7) * 4 + (p & 3);
            int rr = (m >> 3) | ((p >> 2) << 1);
            int wi = lane2 * 4 + rr;
            smw[OFF_A + wi] = q0;
            smw[OFF_A + KSTEPS * 128 + wi] = q1;
        } else if (tid < 144) {
            int m = tid - 128;
            uint32_t q0, q1;
            split2(xcc[m * XROW + 16], 0.0f, q0, q1);
            int wi = 33 * 128 + ((m & 7) * 4) * 4 + (m >> 3);
            smw[OFF_A + wi] = q0;
            smw[OFF_A + KSTEPS * 128 + wi] = q1;
        }
        __syncthreads();

        // ---- prefetch x/cost for t+1 (overlaps mma) ----
        if (tid < 128 && t + 1 < T_STEPS) {
            int b = tid >> 3, q = tid & 7;
            float* dst = xcb + ((t + 1) & 1) * B_PER_CL * XROW + b * XROW;
            const float* xp = x + ((size_t)(bbase + b) * T_STEPS + (t + 1)) * 16;
            dst[2 * q]     = __ldg(xp + 2 * q);
            dst[2 * q + 1] = __ldg(xp + 2 * q + 1);
            if (q == 0) dst[16] = __ldg(cost + (size_t)(bbase + b) * T_STEPS + (t + 1));
        }

        // ---- mma: warp = n-tile x k-half; 17 ksteps x 4 exact passes ----
        float acc[4];
        acc[0] = acc[1] = acc[2] = acc[3] = 0.0f;
        #pragma unroll
        for (int s = 0; s < 17; ++s) {
            int ks = kh2 * 17 + s;
            uint4 I0 = *(const uint4*)&smw[OFF_A + A2W(0, ks, lane)];
            uint4 I1 = *(const uint4*)&smw[OFF_A + A2W(1, ks, lane)];
            uint2 W0 = *(const uint2*)&smw[OFF_W + W_WORD(0, nt, ks, lane, 0)];
            uint2 W1 = *(const uint2*)&smw[OFF_W + W_WORD(1, nt, ks, lane, 0)];
            mma16816(acc, I0, W0);
            mma16816(acc, I1, W0);
            mma16816(acc, I0, W1);
            mma16816(acc, I1, W1);
        }
        {
            int g = lane >> 2, tt = lane & 3;
            int n0 = nt * 8 + 2 * tt;
            *(float2*)&red[kh2 * RQ + g * 68 + n0]       = make_float2(acc[0], acc[1]);
            *(float2*)&red[kh2 * RQ + (g + 8) * 68 + n0] = make_float2(acc[2], acc[3]);
        }
        __syncthreads();

        // ---- reduce 2 k-half partials; publish f32 h + frag-form h ----
        {
            int m = tid >> 5, n0 = (tid & 31) * 2;
            float2 r0 = *(const float2*)&red[m * 68 + n0];
            float2 r1 = *(const float2*)&red[RQ + m * 68 + n0];
            float2 s = make_float2(r0.x + r1.x, r0.y + r1.y);
            float* hdst = (t == T_STEPS - 1) ? (out + (size_t)B_TOT * T_STEPS) : g_hbuf[ppw];
            __stcg((float2*)(hdst + (size_t)(bbase + m) * H_DIM + row0 + n0), s);
            uint32_t q0, q1;
            split2(s.x, s.y, q0, q1);
            int lane2 = (m & 7) * 4 + ((n0 >> 1) & 3);
            int rr = (m >> 3) | (((n0 >> 3) & 1) << 1);
            int widx = ((n0 >> 4) * 32 + lane2) * 4 + rr;   // 0..511 (bounce, reuses A)
            smw[OFF_A + widx] = q0;
            smw[OFF_A + 512 + widx] = q1;
        }
        __syncthreads();
        if (tid < 256) {
            int t2 = tid >> 7, qq = tid & 127;
            uint4 v = *(const uint4*)&smw[OFF_A + t2 * 512 + qq * 4];
            __stcg(((uint4*)&g_hfrag[ppw][clid][t2][(row0 >> 4) * 128]) + qq, v);
        }

        // ---- cluster barrier: publish h_{t+1} before next step reads ----
        asm volatile("barrier.cluster.arrive.aligned;" ::: "memory");
        asm volatile("barrier.cluster.wait.aligned;"   ::: "memory");
    }
}

extern "C" void kernel_launch(void* const* d_in, const int* in_sizes, int n_in,
                              void* d_out, int out_size) {
    const float* x      = (const float*)d_in[0];
    const float* hidden = (const float*)d_in[1];
    const float* cost   = (const float*)d_in[2];
    const float* Wo     = (const float*)d_in[3];
    const float* Wh     = (const float*)d_in[4];
    float* out = (float*)d_out;

    size_t smem = (size_t)SMEM_WORDS * 4;   // ~187.5 KB
    cudaFuncSetAttribute(rnn_mma_kernel, cudaFuncAttributeMaxDynamicSharedMemorySize, (int)smem);
    rnn_mma_kernel<<<128, NTHREADS, smem>>>(x, hidden, cost, Wo, Wh, out);
}

// round 12
// speedup vs baseline: 3.1140x; 1.0712x over previous
#include <cuda_runtime.h>
#include <cstdint>

// Problem constants
#define T_STEPS 2048
#define B_TOT   256
#define H_DIM   512
#define D_IN    529
#define KPAD    544            // padded K cols = 34 k16-steps
#define KSTEPS  34
#define ROWS_PER_CTA 64
#define B_PER_CL 16
#define NCL 16
#define NTHREADS 512
#define XROW 20
#define RQ 1088                // red floats per k-half: 16 batches * 68 stride

// SMEM word (uint32) offsets
#define W_WORDS (2*8*KSTEPS*32*2)     // 2 terms x 8 ntiles x 34 ks x 32 lanes x 2 regs = 34816
#define A_WORDS (2*KSTEPS*32*4)       // 2 terms x 34 ks x 32 lanes x 4 regs = 8704
#define OFF_W 0
#define OFF_A (OFF_W + W_WORDS)
#define OFF_RED (OFF_A + A_WORDS)     // float[2*RQ]
#define OFF_WO (OFF_RED + 2*RQ)       // float[KPAD]
#define OFF_XC (OFF_WO + KPAD)        // float[2*16*XROW]
#define SMEM_WORDS (OFF_XC + 2*B_PER_CL*XROW)

#define W_WORD(term,nt,ks,ln,reg) (((((term)*8+(nt))*KSTEPS+(ks))*32+(ln))*2+(reg))
#define A2W(t2,ks,ln) ((((t2)*KSTEPS+(ks))*32+(ln))*4)

// f32 hidden ping-pong (for o_t and h_final)
__device__ float g_hbuf[2][B_TOT * H_DIM];
// fragment-ready bf16 2-term hidden ping-pong: [pp][cluster][term][32 ks x 32 lanes x 4 regs]
__device__ uint32_t g_hfrag[2][NCL][2][4096];

__device__ __forceinline__ uint32_t f2bf(float f) {
    uint32_t u = __float_as_uint(f);
    return (u + 0x7FFFu + ((u >> 16) & 1u)) >> 16;
}
__device__ __forceinline__ float bf2f(uint32_t b) { return __uint_as_float(b << 16); }

// pack {lo=bf16(a), hi=bf16(b)} in one HW cvt
__device__ __forceinline__ uint32_t cvt2(float a, float b) {
    uint32_t r;
    asm("cvt.rn.satfinite.bf16x2.f32 %0, %1, %2;" : "=r"(r) : "f"(b), "f"(a));
    return r;
}

__device__ __forceinline__ void mma16816(float c[4], uint4 a, uint2 b) {
    asm volatile(
        "mma.sync.aligned.m16n8k16.row.col.f32.bf16.bf16.f32 "
        "{%0,%1,%2,%3}, {%4,%5,%6,%7}, {%8,%9}, {%0,%1,%2,%3};"
        : "+f"(c[0]), "+f"(c[1]), "+f"(c[2]), "+f"(c[3])
        : "r"(a.x), "r"(a.y), "r"(a.z), "r"(a.w), "r"(b.x), "r"(b.y));
}

// split float2 into two packed bf16x2 terms
__device__ __forceinline__ void split2(float v0, float v1, uint32_t& q0, uint32_t& q1) {
    q0 = cvt2(v0, v1);
    float e0 = v0 - __uint_as_float(q0 << 16);
    float e1 = v1 - __uint_as_float(q0 & 0xFFFF0000u);
    q1 = cvt2(e0, e1);
}

extern "C" __global__ void __launch_bounds__(NTHREADS, 1) __cluster_dims__(8, 1, 1)
rnn_mma_kernel(const float* __restrict__ x,       // [B, T, 16]
               const float* __restrict__ hidden,  // [B, 512]
               const float* __restrict__ cost,    // [B, T]
               const float* __restrict__ Wo,      // [1, 529]
               const float* __restrict__ Wh,      // [512, 529]
               float* __restrict__ out)           // [B*T] outs, then [B*512] h_final
{
    extern __shared__ uint32_t smw[];
    float* red  = (float*)(smw + OFF_RED);
    float* WoS  = (float*)(smw + OFF_WO);
    float* xcb  = (float*)(smw + OFF_XC);

    const int tid   = threadIdx.x;
    const int lane  = tid & 31;
    const int w     = tid >> 5;                 // warp 0..15
    const int crank = blockIdx.x & 7;
    const int clid  = blockIdx.x >> 3;
    const int bbase = clid * B_PER_CL;
    const int row0  = crank * ROWS_PER_CTA;

    // ---- one-time: W 2-term bf16 split into fragment-ordered SMEM ----
    for (int idx = tid; idx < ROWS_PER_CTA * KPAD; idx += NTHREADS) {
        int nl = idx / KPAD, c = idx - nl * KPAD;
        float v = (c < D_IN) ? Wh[(size_t)(row0 + nl) * D_IN + c] : 0.0f;
        uint32_t b0 = f2bf(v);
        uint32_t b1 = f2bf(v - bf2f(b0));
        int nt = nl >> 3, gp = nl & 7, ks = c >> 4, kk = c & 15;
        int reg = kk >> 3, tpp = (kk & 7) >> 1, half = kk & 1, lnp = gp * 4 + tpp;
        ((uint16_t*)smw)[(OFF_W + W_WORD(0, nt, ks, lnp, reg)) * 2 + half] = (uint16_t)b0;
        ((uint16_t*)smw)[(OFF_W + W_WORD(1, nt, ks, lnp, reg)) * 2 + half] = (uint16_t)b1;
    }
    for (int idx = tid; idx < A_WORDS; idx += NTHREADS) smw[OFF_A + idx] = 0u;
    for (int idx = tid; idx < KPAD; idx += NTHREADS) WoS[idx] = (idx < D_IN) ? Wo[idx] : 0.0f;
    // f32 h0 for o_t
    for (int idx = tid; idx < 2 * H_DIM; idx += NTHREADS) {
        int bl = idx >> 9, col = idx & (H_DIM - 1);
        size_t off = (size_t)(bbase + crank * 2 + bl) * H_DIM + col;
        g_hbuf[1][off] = hidden[off];
    }
    // frag-form h0: this CTA's 64-row slice
    {
        int m = tid >> 5, n0 = (tid & 31) * 2;
        float v0 = hidden[(size_t)(bbase + m) * H_DIM + row0 + n0];
        float v1 = hidden[(size_t)(bbase + m) * H_DIM + row0 + n0 + 1];
        uint32_t q0, q1;
        split2(v0, v1, q0, q1);
        int lane2 = (m & 7) * 4 + ((n0 >> 1) & 3);
        int rr = (m >> 3) | (((n0 >> 3) & 1) << 1);
        int widx = (row0 >> 4) * 128 + (((n0 >> 4) * 32 + lane2) * 4 + rr);
        g_hfrag[1][clid][0][widx] = q0;
        g_hfrag[1][clid][1][widx] = q1;
    }
    // x/cost t=0
    if (tid < 128) {
        int b = tid >> 3, q = tid & 7;
        const float* xp = x + ((size_t)(bbase + b) * T_STEPS) * 16;
        xcb[b * XROW + 2 * q]     = __ldg(xp + 2 * q);
        xcb[b * XROW + 2 * q + 1] = __ldg(xp + 2 * q + 1);
        if (q == 0) xcb[b * XROW + 16] = __ldg(cost + (size_t)(bbase + b) * T_STEPS);
    }
    __syncthreads();
    asm volatile("barrier.cluster.arrive.aligned;" ::: "memory");
    asm volatile("barrier.cluster.wait.aligned;"   ::: "memory");

    const int nt  = w & 7;        // compute: n-tile (8 rows)
    const int kh2 = w >> 3;       // compute: k-half

    for (int t = 0; t < T_STEPS; ++t) {
        const int ppr = (t + 1) & 1, ppw = t & 1, cur = t & 1;
        const float* xcc = xcb + cur * B_PER_CL * XROW;

        // ---- phase A: staging copy (warps 0-14, batched MLP) || o_t (warp 15) ----
        if (w == 15) {
            int bo = 2 * crank + (lane >> 4), li = lane & 15;
            const float* hrow = g_hbuf[ppr] + (size_t)(bbase + bo) * H_DIM;
            float r = 0.0f;
            #pragma unroll
            for (int j = 0; j < KSTEPS; ++j) {
                int c = li + 16 * j;
                float v;
                if (c < 16)        v = xcc[bo * XROW + c];
                else if (c < 528)  v = __ldcg(hrow + (c - 16));
                else if (c == 528) v = xcc[bo * XROW + 16];
                else               v = 0.0f;
                r += WoS[c] * v;
            }
            r += __shfl_xor_sync(0xffffffffu, r, 1);
            r += __shfl_xor_sync(0xffffffffu, r, 2);
            r += __shfl_xor_sync(0xffffffffu, r, 4);
            r += __shfl_xor_sync(0xffffffffu, r, 8);
            if (li == 0) out[(size_t)(bbase + bo) * T_STEPS + t] = r;
        } else {
            // 2048 uint4 over 480 threads: 4 batched loads + tail (tid<128)
            const uint4* gsrc = (const uint4*)g_hfrag[ppr][clid];
            uint4 v[4];
            #pragma unroll
            for (int i = 0; i < 4; ++i) v[i] = __ldcg(gsrc + tid + 480 * i);
            uint4 v4;
            if (tid < 128) v4 = __ldcg(gsrc + tid + 1920);
            #pragma unroll
            for (int i = 0; i < 4; ++i) {
                int q = tid + 480 * i;
                int t2 = q >> 10, qq = q & 1023;
                *(uint4*)&smw[OFF_A + (t2 * KSTEPS + 1) * 128 + qq * 4] = v[i];
            }
            if (tid < 128) {
                int q = tid + 1920;
                int t2 = q >> 10, qq = q & 1023;
                *(uint4*)&smw[OFF_A + (t2 * KSTEPS + 1) * 128 + qq * 4] = v4;
            }
        }
        // x frags (ks0) and cost frags (ks33)
        if (tid < 128) {
            int m = tid >> 3, p = tid & 7;
            uint32_t q0, q1;
            split2(xcc[m * XROW + 2 * p], xcc[m * XROW + 2 * p + 1], q0, q1);
            int lane2 = (m & 7) * 4 + (p & 3);
            int rr = (m >> 3) | ((p >> 2) << 1);
            int wi = lane2 * 4 + rr;
            smw[OFF_A + wi] = q0;
            smw[OFF_A + KSTEPS * 128 + wi] = q1;
        } else if (tid < 144) {
            int m = tid - 128;
            uint32_t q0, q1;
            split2(xcc[m * XROW + 16], 0.0f, q0, q1);
            int wi = 33 * 128 + ((m & 7) * 4) * 4 + (m >> 3);
            smw[OFF_A + wi] = q0;
            smw[OFF_A + KSTEPS * 128 + wi] = q1;
        }
        __syncthreads();

        // ---- prefetch x/cost for t+1 (overlaps mma) ----
        if (tid < 128 && t + 1 < T_STEPS) {
            int b = tid >> 3, q = tid & 7;
            float* dst = xcb + ((t + 1) & 1) * B_PER_CL * XROW + b * XROW;
            const float* xp = x + ((size_t)(bbase + b) * T_STEPS + (t + 1)) * 16;
            dst[2 * q]     = __ldg(xp + 2 * q);
            dst[2 * q + 1] = __ldg(xp + 2 * q + 1);
            if (q == 0) dst[16] = __ldg(cost + (size_t)(bbase + b) * T_STEPS + (t + 1));
        }

        // ---- mma: warp = n-tile x k-half; 17 ksteps x 4 passes, 4 indep acc chains ----
        float a00[4] = {0,0,0,0}, a01[4] = {0,0,0,0}, a10[4] = {0,0,0,0}, a11[4] = {0,0,0,0};
        #pragma unroll
        for (int s = 0; s < 17; ++s) {
            int ks = kh2 * 17 + s;
            uint4 I0 = *(const uint4*)&smw[OFF_A + A2W(0, ks, lane)];
            uint4 I1 = *(const uint4*)&smw[OFF_A + A2W(1, ks, lane)];
            uint2 W0 = *(const uint2*)&smw[OFF_W + W_WORD(0, nt, ks, lane, 0)];
            uint2 W1 = *(const uint2*)&smw[OFF_W + W_WORD(1, nt, ks, lane, 0)];
            mma16816(a00, I0, W0);
            mma16816(a10, I1, W0);
            mma16816(a01, I0, W1);
            mma16816(a11, I1, W1);
        }
        {
            float acc[4];
            #pragma unroll
            for (int i = 0; i < 4; ++i)
                acc[i] = (a00[i] + a01[i]) + (a10[i] + a11[i]);
            int g = lane >> 2, tt = lane & 3;
            int n0 = nt * 8 + 2 * tt;
            *(float2*)&red[kh2 * RQ + g * 68 + n0]       = make_float2(acc[0], acc[1]);
            *(float2*)&red[kh2 * RQ + (g + 8) * 68 + n0] = make_float2(acc[2], acc[3]);
        }
        __syncthreads();

        // ---- reduce 2 k-half partials; publish f32 h + frag-form h ----
        {
            int m = tid >> 5, n0 = (tid & 31) * 2;
            float2 r0 = *(const float2*)&red[m * 68 + n0];
            float2 r1 = *(const float2*)&red[RQ + m * 68 + n0];
            float2 s = make_float2(r0.x + r1.x, r0.y + r1.y);
            float* hdst = (t == T_STEPS - 1) ? (out + (size_t)B_TOT * T_STEPS) : g_hbuf[ppw];
            __stcg((float2*)(hdst + (size_t)(bbase + m) * H_DIM + row0 + n0), s);
            uint32_t q0, q1;
            split2(s.x, s.y, q0, q1);
            int lane2 = (m & 7) * 4 + ((n0 >> 1) & 3);
            int rr = (m >> 3) | (((n0 >> 3) & 1) << 1);
            int widx = ((n0 >> 4) * 32 + lane2) * 4 + rr;   // 0..511 (bounce, reuses A)
            smw[OFF_A + widx] = q0;
            smw[OFF_A + 512 + widx] = q1;
        }
        __syncthreads();
        if (tid < 256) {
            int t2 = tid >> 7, qq = tid & 127;
            uint4 v = *(const uint4*)&smw[OFF_A + t2 * 512 + qq * 4];
            __stcg(((uint4*)&g_hfrag[ppw][clid][t2][(row0 >> 4) * 128]) + qq, v);
        }

        // ---- cluster barrier: publish h_{t+1} before next step reads ----
        asm volatile("barrier.cluster.arrive.aligned;" ::: "memory");
        asm volatile("barrier.cluster.wait.aligned;"   ::: "memory");
    }
}

extern "C" void kernel_launch(void* const* d_in, const int* in_sizes, int n_in,
                              void* d_out, int out_size) {
    const float* x      = (const float*)d_in[0];
    const float* hidden = (const float*)d_in[1];
    const float* cost   = (const float*)d_in[2];
    const float* Wo     = (const float*)d_in[3];
    const float* Wh     = (const float*)d_in[4];
    float* out = (float*)d_out;

    size_t smem = (size_t)SMEM_WORDS * 4;   // ~187.5 KB
    cudaFuncSetAttribute(rnn_mma_kernel, cudaFuncAttributeMaxDynamicSharedMemorySize, (int)smem);
    rnn_mma_kernel<<<128, NTHREADS, smem>>>(x, hidden, cost, Wo, Wh, out);
}